// round 11
// baseline (speedup 1.0000x reference)
#include <cuda_runtime.h>
#include <cuda_fp16.h>
#include <cstdint>

// ---------------------------------------------------------------------------
// GCN (3-layer) on GB300 — CSR gather, fp16 intermediates, overlapped CSR build.
//   L1: xw = H @ W (UNscaled, fp16); gather applies dinv[r] per neighbor.
//   L2/3: xw = (H @ W) * dinv[row] (fp16), gather uses prescaled rows.
//   out[c] = relu( (self + sum) * dinv[c] + b )
//   CSR build (deg->scan->fill) runs on a side stream concurrent with GEMM1.
// ---------------------------------------------------------------------------

#define N_MAX 100000
#define E_MAX 1600000

static __device__ __align__(256) __half2 g_xw[(size_t)N_MAX * 32];   // stride 32
static __device__ __align__(256) __half2 g_h[(size_t)N_MAX * 32];    // stride 32
static __device__ __align__(256) float g_dinv[N_MAX];
static __device__ int g_degi[N_MAX];
static __device__ int g_cursor[N_MAX];
static __device__ int g_ptr[N_MAX + 1];
static __device__ unsigned long long g_scan_state[512];
static __device__ int g_erow[E_MAX];
static __device__ int g_mode;  // 0 = int64 indices, 1 = int32 indices

// ---------------- dtype detection ----------------
__global__ void detect_mode_kernel(const void* ei, int cnt64, int n) {
    __shared__ int bad;
    if (threadIdx.x == 0) bad = 0;
    __syncthreads();
    const long long* p = (const long long*)ei;
    int cnt = min(cnt64, 1024);
    for (int i = threadIdx.x; i < cnt; i += blockDim.x) {
        unsigned long long v = (unsigned long long)p[i];
        if (v >= (unsigned long long)n) atomicOr(&bad, 1);
    }
    __syncthreads();
    if (threadIdx.x == 0) g_mode = bad ? 1 : 0;
}

__device__ __forceinline__ int edge_idx(const void* ei, long long pos, int mode) {
    return mode ? ((const int*)ei)[pos] : (int)((const long long*)ei)[pos];
}

// ---------------- CSR build ----------------

__global__ void deg_count_kernel(int* degi, const void* ei, int E, int n) {
    int e = blockIdx.x * blockDim.x + threadIdx.x;
    if (e < E) {
        int mode = g_mode;
        unsigned c = (unsigned)edge_idx(ei, (long long)E + e, mode);  // col
        if (c < (unsigned)n) atomicAdd(&degi[c], 1);
    }
}

// Single-pass scan (decoupled lookback) + ptr/cursor/dinv epilogue.
// All 391 blocks co-resident -> spin-wait is safe; output deterministic.
__global__ void scan_onepass_kernel(const int* __restrict__ degi,
                                    int* __restrict__ ptr,
                                    int* __restrict__ cursor,
                                    float* __restrict__ dinv,
                                    unsigned long long* state,
                                    int n, int E) {
    __shared__ int s[256];
    __shared__ int blk_prefix;
    const int b = blockIdx.x;
    const int i = b * 256 + threadIdx.x;
    const int v = (i < n) ? degi[i] : 0;
    s[threadIdx.x] = v;
    __syncthreads();
    for (int off = 1; off < 256; off <<= 1) {
        int t = (threadIdx.x >= off) ? s[threadIdx.x - off] : 0;
        __syncthreads();
        s[threadIdx.x] += t;
        __syncthreads();
    }
    const int agg = s[255];
    if (threadIdx.x == 0) {
        if (b == 0) {
            atomicExch(&state[0], (2ull << 32) | (unsigned)agg);
            blk_prefix = 0;
        } else {
            atomicExch(&state[b], (1ull << 32) | (unsigned)agg);
            int pre = 0;
            for (int look = b - 1; look >= 0; look--) {
                unsigned long long st;
                do { st = atomicAdd(&state[look], 0ull); } while ((st >> 32) == 0ull);
                pre += (int)(unsigned)st;
                if ((st >> 32) == 2ull) break;
            }
            atomicExch(&state[b], (2ull << 32) | (unsigned)(pre + agg));
            blk_prefix = pre;
        }
    }
    __syncthreads();
    if (i < n) {
        int p = blk_prefix + s[threadIdx.x] - v;   // exclusive
        ptr[i] = p;
        cursor[i] = p;
        dinv[i] = rsqrtf(1.0f + (float)degi[i]);   // +1 self loop
    }
    if (i == 0) ptr[n] = E;
}

__global__ void fill_kernel(const void* ei, int* cursor, int* erow, int E, int n) {
    int e = blockIdx.x * blockDim.x + threadIdx.x;
    if (e < E) {
        int mode = g_mode;
        unsigned r = (unsigned)edge_idx(ei, e, mode);
        unsigned c = (unsigned)edge_idx(ei, (long long)E + e, mode);
        if (r >= (unsigned)n || c >= (unsigned)n) return;
        int pos = atomicAdd(&cursor[c], 1);
        erow[pos] = (int)r;
    }
}

// ---------------- GEMM (+ optional dinv[row] scale) -> half2, stride 32 -----

__device__ __forceinline__ void fma2(unsigned long long& d,
                                     unsigned long long a,
                                     unsigned long long b) {
    asm("fma.rn.f32x2 %0, %1, %2, %3;" : "=l"(d) : "l"(a), "l"(b), "l"(d));
}

template <int DIN, int DOUT, bool HALF_IN, bool SCALE>
__global__ void gemm_kernel(const void* __restrict__ Xv,
                            const float* __restrict__ W,
                            const float* __restrict__ dinv,
                            __half2* __restrict__ xwh,
                            int M) {
    __shared__ __align__(16) float Ws[DIN * DOUT];
    const int tid = threadIdx.x;           // 0..127
    const int row = blockIdx.x * 128 + tid;

    for (int i = tid; i < DIN * DOUT; i += 128) Ws[i] = W[i];
    __syncthreads();

    unsigned long long a2[DOUT / 2];
#pragma unroll
    for (int j = 0; j < DOUT / 2; j++) a2[j] = 0ull;

    const bool act = (row < M);

#pragma unroll
    for (int k0 = 0; k0 < DIN; k0 += 16) {
        float xr[16];
        if (act) {
            if (HALF_IN) {
                const uint4* src = (const uint4*)((const __half*)Xv + (size_t)row * DIN + k0);
                uint4 u0 = __ldg(src);
                uint4 u1 = __ldg(src + 1);
                const unsigned* uu = &u0.x;
#pragma unroll
                for (int q = 0; q < 4; q++) {
                    float2 f = __half22float2(*(const __half2*)&uu[q]);
                    xr[q * 2] = f.x; xr[q * 2 + 1] = f.y;
                }
                const unsigned* vv = &u1.x;
#pragma unroll
                for (int q = 0; q < 4; q++) {
                    float2 f = __half22float2(*(const __half2*)&vv[q]);
                    xr[8 + q * 2] = f.x; xr[8 + q * 2 + 1] = f.y;
                }
            } else {
                const float4* src = (const float4*)((const float*)Xv + (size_t)row * DIN + k0);
#pragma unroll
                for (int q = 0; q < 4; q++) {
                    float4 v = __ldg(src + q);
                    xr[q * 4] = v.x; xr[q * 4 + 1] = v.y;
                    xr[q * 4 + 2] = v.z; xr[q * 4 + 3] = v.w;
                }
            }
        } else {
#pragma unroll
            for (int q = 0; q < 16; q++) xr[q] = 0.f;
        }
#pragma unroll
        for (int k = 0; k < 16; k++) {
            unsigned long long xv2;
            asm("mov.b64 %0, {%1, %2};" : "=l"(xv2) : "f"(xr[k]), "f"(xr[k]));
            const float* wrow = &Ws[(k0 + k) * DOUT];
#pragma unroll
            for (int j = 0; j < DOUT; j += 4) {
                ulonglong2 ww = *(const ulonglong2*)&wrow[j];
                fma2(a2[j / 2],     xv2, ww.x);
                fma2(a2[j / 2 + 1], xv2, ww.y);
            }
        }
    }

    if (act) {
        float s = SCALE ? dinv[row] : 1.0f;
        __half2* dst = xwh + (size_t)row * 32;      // padded stride
#pragma unroll
        for (int p = 0; p < DOUT / 2; p += 2) {
            float x0, x1, x2, x3;
            asm("mov.b64 {%0, %1}, %2;" : "=f"(x0), "=f"(x1) : "l"(a2[p]));
            asm("mov.b64 {%0, %1}, %2;" : "=f"(x2), "=f"(x3) : "l"(a2[p + 1]));
            uint2 pack;
            __half2 h0 = __floats2half2_rn(x0 * s, x1 * s);
            __half2 h1 = __floats2half2_rn(x2 * s, x3 * s);
            pack.x = *(unsigned*)&h0;
            pack.y = *(unsigned*)&h1;
            *(uint2*)&dst[p] = pack;
        }
    }
}

// ---------------- gather-reduce + fused epilogue (warp per node) ------------
// NSCALE: xw rows are UNscaled; multiply each neighbor by dinv[r] (broadcast).

template <bool NSCALE>
__global__ void gather64h_kernel(const __half2* __restrict__ xwh,
                                 const int* __restrict__ ptr,
                                 const int* __restrict__ erow,
                                 const float* __restrict__ dinv,
                                 const float* __restrict__ b,
                                 __half2* __restrict__ out,
                                 int n) {
    int lane = threadIdx.x & 31;
    int node = blockIdx.x * 8 + (threadIdx.x >> 5);
    if (node >= n) return;

    int start = __ldg(&ptr[node]);
    int end   = __ldg(&ptr[node + 1]);
    float sn = __ldg(&dinv[node]);

    float2 self = __half22float2(__ldg(&xwh[(size_t)node * 32 + lane]));
    float2 acc;
    if (NSCALE) { acc.x = self.x * sn; acc.y = self.y * sn; }
    else        { acc = self; }

    int cnt = end - start;
    int j = start, j8 = start + (cnt & ~7);
    for (; j < j8; j += 8) {
        int ids[8];
#pragma unroll
        for (int k = 0; k < 8; k++) ids[k] = __ldg(&erow[j + k]);
#pragma unroll
        for (int k = 0; k < 8; k++) {
            float2 f = __half22float2(__ldg(&xwh[(size_t)ids[k] * 32 + lane]));
            if (NSCALE) {
                float sr = __ldg(&dinv[ids[k]]);
                acc.x += f.x * sr; acc.y += f.y * sr;
            } else {
                acc.x += f.x; acc.y += f.y;
            }
        }
    }
    for (; j < end; j++) {
        int id = __ldg(&erow[j]);
        float2 f = __half22float2(__ldg(&xwh[(size_t)id * 32 + lane]));
        if (NSCALE) {
            float sr = __ldg(&dinv[id]);
            acc.x += f.x * sr; acc.y += f.y * sr;
        } else {
            acc.x += f.x; acc.y += f.y;
        }
    }

    float2 bb = __ldg((const float2*)b + lane);
    float ox = fmaxf(acc.x * sn + bb.x, 0.f);
    float oy = fmaxf(acc.y * sn + bb.y, 0.f);
    out[(size_t)node * 32 + lane] = __floats2half2_rn(ox, oy);
}

// D=40 final layer: 20 threads/node, xw stride 32 half2 (prescaled), fp32 out.

__global__ void gather40_kernel(const __half2* __restrict__ xwh,
                                const int* __restrict__ ptr,
                                const int* __restrict__ erow,
                                const float* __restrict__ dinv,
                                const float* __restrict__ b,
                                float* __restrict__ out,
                                int n) {
    int tid = threadIdx.x;
    if (tid >= 240) return;                  // 12 nodes * 20 threads
    int nl = tid / 20;
    int lane = tid - nl * 20;                // feature pair 0..19
    int node = blockIdx.x * 12 + nl;
    if (node >= n) return;

    int start = __ldg(&ptr[node]);
    int end   = __ldg(&ptr[node + 1]);

    float2 acc = __half22float2(__ldg(&xwh[(size_t)node * 32 + lane]));  // self

    int cnt = end - start;
    int j = start, j8 = start + (cnt & ~7);
    for (; j < j8; j += 8) {
        int ids[8];
#pragma unroll
        for (int k = 0; k < 8; k++) ids[k] = __ldg(&erow[j + k]);
#pragma unroll
        for (int k = 0; k < 8; k++) {
            float2 f = __half22float2(__ldg(&xwh[(size_t)ids[k] * 32 + lane]));
            acc.x += f.x; acc.y += f.y;
        }
    }
    for (; j < end; j++) {
        float2 f = __half22float2(__ldg(&xwh[(size_t)__ldg(&erow[j]) * 32 + lane]));
        acc.x += f.x; acc.y += f.y;
    }

    float s = __ldg(&dinv[node]);
    float2 bb = __ldg((const float2*)b + lane);
    float2 o = make_float2(acc.x * s + bb.x, acc.y * s + bb.y);
    ((float2*)out)[(size_t)node * 20 + lane] = o;
}

// ---------------- launch ----------------

extern "C" void kernel_launch(void* const* d_in, const int* in_sizes, int n_in,
                              void* d_out, int out_size) {
    int i_x = -1, i_ei = -1, i_w1 = -1, i_w2 = -1, i_w3 = -1;
    int i_b1 = -1, i_b2 = -1, i_b3 = -1;
    for (int i = 0; i < n_in; i++) {
        int s = in_sizes[i];
        if      (s == 12800000) i_x  = i;
        else if (s == 3200000)  i_ei = i;
        else if (s == 8192)     i_w1 = i;
        else if (s == 4096)     i_w2 = i;
        else if (s == 2560)     i_w3 = i;
        else if (s == 40)       i_b3 = i;
        else if (s == 64)       { if (i_b1 < 0) i_b1 = i; else i_b2 = i; }
    }
    if (i_x < 0 || i_ei < 0 || i_w1 < 0 || i_b1 < 0 || i_w2 < 0 ||
        i_b2 < 0 || i_w3 < 0 || i_b3 < 0) {
        i_x = 0; i_ei = 1; i_w1 = 2; i_b1 = 3; i_w2 = 4; i_b2 = 5; i_w3 = 6; i_b3 = 7;
    }

    const float* x  = (const float*)d_in[i_x];
    const void*  ei = d_in[i_ei];
    const float* W1 = (const float*)d_in[i_w1];
    const float* b1 = (const float*)d_in[i_b1];
    const float* W2 = (const float*)d_in[i_w2];
    const float* b2 = (const float*)d_in[i_b2];
    const float* W3 = (const float*)d_in[i_w3];
    const float* b3 = (const float*)d_in[i_b3];

    const int M = in_sizes[i_x] / 128;     // 100000
    const int E = in_sizes[i_ei] / 2;      // 1600000
    float* out = (float*)d_out;

    __half2 *pXw, *pH;
    float* pDinv;
    int *pDeg, *pCur, *pPtr, *pErow;
    unsigned long long* pState;
    cudaGetSymbolAddress((void**)&pXw, g_xw);
    cudaGetSymbolAddress((void**)&pH, g_h);
    cudaGetSymbolAddress((void**)&pDinv, g_dinv);
    cudaGetSymbolAddress((void**)&pDeg, g_degi);
    cudaGetSymbolAddress((void**)&pCur, g_cursor);
    cudaGetSymbolAddress((void**)&pPtr, g_ptr);
    cudaGetSymbolAddress((void**)&pState, g_scan_state);
    cudaGetSymbolAddress((void**)&pErow, g_erow);

    const int T = 256;
    const int nbN = (M + 255) / 256;
    const int nbE = (E + T - 1) / T;
    const int gM  = (M + 127) / 128;
    const int g64 = (M + 7) / 8;
    const int g40 = (M + 11) / 12;

    cudaStream_t s2;
    cudaEvent_t evD, evF;
    bool forked = (cudaStreamCreateWithFlags(&s2, cudaStreamNonBlocking) == cudaSuccess) &&
                  (cudaEventCreateWithFlags(&evD, cudaEventDisableTiming) == cudaSuccess) &&
                  (cudaEventCreateWithFlags(&evF, cudaEventDisableTiming) == cudaSuccess);

    if (forked) {
        // side stream: complete CSR build; main stream: GEMM1 (no dinv needed)
        cudaEventRecord(evD, 0);
        cudaStreamWaitEvent(s2, evD, 0);
        detect_mode_kernel<<<1, 256, 0, s2>>>(ei, 2 * E, M);
        cudaMemsetAsync(pDeg, 0, (size_t)M * sizeof(int), s2);
        cudaMemsetAsync(pState, 0, 512 * sizeof(unsigned long long), s2);
        deg_count_kernel<<<nbE, T, 0, s2>>>(pDeg, ei, E, M);
        scan_onepass_kernel<<<nbN, 256, 0, s2>>>(pDeg, pPtr, pCur, pDinv, pState, M, E);
        fill_kernel<<<nbE, T, 0, s2>>>(ei, pCur, pErow, E, M);
        cudaEventRecord(evF, s2);

        gemm_kernel<128, 64, false, false><<<gM, 128>>>(x, W1, pDinv, pXw, M);
        cudaStreamWaitEvent(0, evF, 0);
    } else {
        detect_mode_kernel<<<1, 256>>>(ei, 2 * E, M);
        cudaMemsetAsync(pDeg, 0, (size_t)M * sizeof(int), 0);
        cudaMemsetAsync(pState, 0, 512 * sizeof(unsigned long long), 0);
        deg_count_kernel<<<nbE, T>>>(pDeg, ei, E, M);
        scan_onepass_kernel<<<nbN, 256>>>(pDeg, pPtr, pCur, pDinv, pState, M, E);
        fill_kernel<<<nbE, T>>>(ei, pCur, pErow, E, M);
        gemm_kernel<128, 64, false, false><<<gM, 128>>>(x, W1, pDinv, pXw, M);
    }

    // Layer 1 aggregation (per-neighbor dinv scaling) -> h (fp16)
    gather64h_kernel<true><<<g64, 256>>>(pXw, pPtr, pErow, pDinv, b1, pH, M);

    // Layer 2 (prescaled)
    gemm_kernel<64, 64, true, true><<<gM, 128>>>(pH, W2, pDinv, pXw, M);
    gather64h_kernel<false><<<g64, 256>>>(pXw, pPtr, pErow, pDinv, b2, pH, M);

    // Layer 3 (DOUT=40, padded stride, prescaled)
    gemm_kernel<64, 40, true, true><<<gM, 128>>>(pH, W3, pDinv, pXw, M);
    gather40_kernel<<<g40, 256>>>(pXw, pPtr, pErow, pDinv, b3, out, M);
}

// round 12
// speedup vs baseline: 1.5003x; 1.5003x over previous
#include <cuda_runtime.h>
#include <cuda_fp16.h>
#include <cstdint>

// ---------------------------------------------------------------------------
// GCN (3-layer) on GB300 — CSR gather, fp16 intermediates.
//   L1: xw = H @ W (UNscaled fp16); gather1 applies dinv[neighbor] per edge.
//   L2/3: xw = (H @ W) * dinv[row] (fp16); gathers add prescaled rows.
//   out[c] = relu( (self + sum) * dinv[c] + b )
//   Full CSR build runs on a side stream concurrent with GEMM1.
//   Scan is the chained 3-kernel version (no spin-waits -> concurrency-safe).
// ---------------------------------------------------------------------------

#define N_MAX 100000
#define E_MAX 1600000

static __device__ __align__(256) __half2 g_xw[(size_t)N_MAX * 32];   // stride 32
static __device__ __align__(256) __half2 g_h[(size_t)N_MAX * 32];    // stride 32
static __device__ __align__(256) float g_dinv[N_MAX];
static __device__ int g_degi[N_MAX];
static __device__ int g_cursor[N_MAX];
static __device__ int g_ptr[N_MAX + 1];
static __device__ int g_bsum[1024];
static __device__ int g_erow[E_MAX];
static __device__ int g_mode;  // 0 = int64 indices, 1 = int32 indices

// ---------------- dtype detection ----------------
__global__ void detect_mode_kernel(const void* ei, int cnt64, int n) {
    __shared__ int bad;
    if (threadIdx.x == 0) bad = 0;
    __syncthreads();
    const long long* p = (const long long*)ei;
    int cnt = min(cnt64, 1024);
    for (int i = threadIdx.x; i < cnt; i += blockDim.x) {
        unsigned long long v = (unsigned long long)p[i];
        if (v >= (unsigned long long)n) atomicOr(&bad, 1);
    }
    __syncthreads();
    if (threadIdx.x == 0) g_mode = bad ? 1 : 0;
}

__device__ __forceinline__ int edge_idx(const void* ei, long long pos, int mode) {
    return mode ? ((const int*)ei)[pos] : (int)((const long long*)ei)[pos];
}

// ---------------- CSR build ----------------

__global__ void deg_count_kernel(int* degi, const void* ei, int E, int n) {
    int e = blockIdx.x * blockDim.x + threadIdx.x;
    if (e < E) {
        int mode = g_mode;
        unsigned c = (unsigned)edge_idx(ei, (long long)E + e, mode);  // col
        if (c < (unsigned)n) atomicAdd(&degi[c], 1);
    }
}

__global__ void scanA_kernel(const int* degi, int* ptr, int* bsum, int n) {
    __shared__ int s[256];
    int i = blockIdx.x * 256 + threadIdx.x;
    int v = (i < n) ? degi[i] : 0;
    s[threadIdx.x] = v;
    __syncthreads();
    for (int off = 1; off < 256; off <<= 1) {
        int t = (threadIdx.x >= off) ? s[threadIdx.x - off] : 0;
        __syncthreads();
        s[threadIdx.x] += t;
        __syncthreads();
    }
    if (i < n) ptr[i] = s[threadIdx.x] - v;   // exclusive within block
    if (threadIdx.x == 255) bsum[blockIdx.x] = s[255];
}

__global__ void scanB_kernel(int* bsum, int nb) {
    __shared__ int s[1024];
    int v = (threadIdx.x < nb) ? bsum[threadIdx.x] : 0;
    s[threadIdx.x] = v;
    __syncthreads();
    for (int off = 1; off < 1024; off <<= 1) {
        int t = (threadIdx.x >= off) ? s[threadIdx.x - off] : 0;
        __syncthreads();
        s[threadIdx.x] += t;
        __syncthreads();
    }
    if (threadIdx.x < nb) bsum[threadIdx.x] = s[threadIdx.x] - v;  // exclusive
}

// scanC + dinv + cursor init, fused (all node-indexed).
__global__ void scanC_fused_kernel(int* ptr, const int* bsum, int* cursor,
                                   float* dinv, const int* degi, int n, int E) {
    int i = blockIdx.x * 256 + threadIdx.x;
    if (i < n) {
        int p = ptr[i] + bsum[blockIdx.x];
        ptr[i] = p;
        cursor[i] = p;                               // fill writes from here
        dinv[i] = rsqrtf(1.0f + (float)degi[i]);     // +1 self loop
    }
    if (i == 0) ptr[n] = E;
}

__global__ void fill_kernel(const void* ei, int* cursor, int* erow, int E, int n) {
    int e = blockIdx.x * blockDim.x + threadIdx.x;
    if (e < E) {
        int mode = g_mode;
        unsigned r = (unsigned)edge_idx(ei, e, mode);
        unsigned c = (unsigned)edge_idx(ei, (long long)E + e, mode);
        if (r >= (unsigned)n || c >= (unsigned)n) return;
        int pos = atomicAdd(&cursor[c], 1);
        erow[pos] = (int)r;
    }
}

// ---------------- GEMM (+ optional dinv[row] scale) -> half2, stride 32 -----

__device__ __forceinline__ void fma2(unsigned long long& d,
                                     unsigned long long a,
                                     unsigned long long b) {
    asm("fma.rn.f32x2 %0, %1, %2, %3;" : "=l"(d) : "l"(a), "l"(b), "l"(d));
}

template <int DIN, int DOUT, bool HALF_IN, bool SCALE>
__global__ void gemm_kernel(const void* __restrict__ Xv,
                            const float* __restrict__ W,
                            const float* __restrict__ dinv,
                            __half2* __restrict__ xwh,
                            int M) {
    __shared__ __align__(16) float Ws[DIN * DOUT];
    const int tid = threadIdx.x;           // 0..127
    const int row = blockIdx.x * 128 + tid;

    for (int i = tid; i < DIN * DOUT; i += 128) Ws[i] = W[i];
    __syncthreads();

    unsigned long long a2[DOUT / 2];
#pragma unroll
    for (int j = 0; j < DOUT / 2; j++) a2[j] = 0ull;

    const bool act = (row < M);

#pragma unroll
    for (int k0 = 0; k0 < DIN; k0 += 16) {
        float xr[16];
        if (act) {
            if (HALF_IN) {
                const uint4* src = (const uint4*)((const __half*)Xv + (size_t)row * DIN + k0);
                uint4 u0 = __ldg(src);
                uint4 u1 = __ldg(src + 1);
                const unsigned* uu = &u0.x;
#pragma unroll
                for (int q = 0; q < 4; q++) {
                    float2 f = __half22float2(*(const __half2*)&uu[q]);
                    xr[q * 2] = f.x; xr[q * 2 + 1] = f.y;
                }
                const unsigned* vv = &u1.x;
#pragma unroll
                for (int q = 0; q < 4; q++) {
                    float2 f = __half22float2(*(const __half2*)&vv[q]);
                    xr[8 + q * 2] = f.x; xr[8 + q * 2 + 1] = f.y;
                }
            } else {
                const float4* src = (const float4*)((const float*)Xv + (size_t)row * DIN + k0);
#pragma unroll
                for (int q = 0; q < 4; q++) {
                    float4 v = __ldg(src + q);
                    xr[q * 4] = v.x; xr[q * 4 + 1] = v.y;
                    xr[q * 4 + 2] = v.z; xr[q * 4 + 3] = v.w;
                }
            }
        } else {
#pragma unroll
            for (int q = 0; q < 16; q++) xr[q] = 0.f;
        }
#pragma unroll
        for (int k = 0; k < 16; k++) {
            unsigned long long xv2;
            asm("mov.b64 %0, {%1, %2};" : "=l"(xv2) : "f"(xr[k]), "f"(xr[k]));
            const float* wrow = &Ws[(k0 + k) * DOUT];
#pragma unroll
            for (int j = 0; j < DOUT; j += 4) {
                ulonglong2 ww = *(const ulonglong2*)&wrow[j];
                fma2(a2[j / 2],     xv2, ww.x);
                fma2(a2[j / 2 + 1], xv2, ww.y);
            }
        }
    }

    if (act) {
        float s = SCALE ? dinv[row] : 1.0f;
        __half2* dst = xwh + (size_t)row * 32;      // padded stride
#pragma unroll
        for (int p = 0; p < DOUT / 2; p += 2) {
            float x0, x1, x2, x3;
            asm("mov.b64 {%0, %1}, %2;" : "=f"(x0), "=f"(x1) : "l"(a2[p]));
            asm("mov.b64 {%0, %1}, %2;" : "=f"(x2), "=f"(x3) : "l"(a2[p + 1]));
            uint2 pack;
            __half2 h0 = __floats2half2_rn(x0 * s, x1 * s);
            __half2 h1 = __floats2half2_rn(x2 * s, x3 * s);
            pack.x = *(unsigned*)&h0;
            pack.y = *(unsigned*)&h1;
            *(uint2*)&dst[p] = pack;
        }
    }
}

// ---------------- gather-reduce + fused epilogue (warp per node) ------------
// NSCALE: xw rows are UNscaled; multiply each neighbor by dinv[r] (broadcast).

template <bool NSCALE>
__global__ void gather64h_kernel(const __half2* __restrict__ xwh,
                                 const int* __restrict__ ptr,
                                 const int* __restrict__ erow,
                                 const float* __restrict__ dinv,
                                 const float* __restrict__ b,
                                 __half2* __restrict__ out,
                                 int n) {
    int lane = threadIdx.x & 31;
    int node = blockIdx.x * 8 + (threadIdx.x >> 5);
    if (node >= n) return;

    int start = __ldg(&ptr[node]);
    int end   = __ldg(&ptr[node + 1]);
    float sn = __ldg(&dinv[node]);

    float2 self = __half22float2(__ldg(&xwh[(size_t)node * 32 + lane]));
    float2 acc;
    if (NSCALE) { acc.x = self.x * sn; acc.y = self.y * sn; }
    else        { acc = self; }

    int cnt = end - start;
    int j = start, j8 = start + (cnt & ~7);
    for (; j < j8; j += 8) {
        int ids[8];
#pragma unroll
        for (int k = 0; k < 8; k++) ids[k] = __ldg(&erow[j + k]);
#pragma unroll
        for (int k = 0; k < 8; k++) {
            float2 f = __half22float2(__ldg(&xwh[(size_t)ids[k] * 32 + lane]));
            if (NSCALE) {
                float sr = __ldg(&dinv[ids[k]]);
                acc.x += f.x * sr; acc.y += f.y * sr;
            } else {
                acc.x += f.x; acc.y += f.y;
            }
        }
    }
    for (; j < end; j++) {
        int id = __ldg(&erow[j]);
        float2 f = __half22float2(__ldg(&xwh[(size_t)id * 32 + lane]));
        if (NSCALE) {
            float sr = __ldg(&dinv[id]);
            acc.x += f.x * sr; acc.y += f.y * sr;
        } else {
            acc.x += f.x; acc.y += f.y;
        }
    }

    float2 bb = __ldg((const float2*)b + lane);
    float ox = fmaxf(acc.x * sn + bb.x, 0.f);
    float oy = fmaxf(acc.y * sn + bb.y, 0.f);
    out[(size_t)node * 32 + lane] = __floats2half2_rn(ox, oy);
}

// D=40 final layer: 20 threads/node, xw stride 32 half2 (prescaled), fp32 out.

__global__ void gather40_kernel(const __half2* __restrict__ xwh,
                                const int* __restrict__ ptr,
                                const int* __restrict__ erow,
                                const float* __restrict__ dinv,
                                const float* __restrict__ b,
                                float* __restrict__ out,
                                int n) {
    int tid = threadIdx.x;
    if (tid >= 240) return;                  // 12 nodes * 20 threads
    int nl = tid / 20;
    int lane = tid - nl * 20;                // feature pair 0..19
    int node = blockIdx.x * 12 + nl;
    if (node >= n) return;

    int start = __ldg(&ptr[node]);
    int end   = __ldg(&ptr[node + 1]);

    float2 acc = __half22float2(__ldg(&xwh[(size_t)node * 32 + lane]));  // self

    int cnt = end - start;
    int j = start, j8 = start + (cnt & ~7);
    for (; j < j8; j += 8) {
        int ids[8];
#pragma unroll
        for (int k = 0; k < 8; k++) ids[k] = __ldg(&erow[j + k]);
#pragma unroll
        for (int k = 0; k < 8; k++) {
            float2 f = __half22float2(__ldg(&xwh[(size_t)ids[k] * 32 + lane]));
            acc.x += f.x; acc.y += f.y;
        }
    }
    for (; j < end; j++) {
        float2 f = __half22float2(__ldg(&xwh[(size_t)__ldg(&erow[j]) * 32 + lane]));
        acc.x += f.x; acc.y += f.y;
    }

    float s = __ldg(&dinv[node]);
    float2 bb = __ldg((const float2*)b + lane);
    float2 o = make_float2(acc.x * s + bb.x, acc.y * s + bb.y);
    ((float2*)out)[(size_t)node * 20 + lane] = o;
}

// ---------------- launch ----------------

extern "C" void kernel_launch(void* const* d_in, const int* in_sizes, int n_in,
                              void* d_out, int out_size) {
    int i_x = -1, i_ei = -1, i_w1 = -1, i_w2 = -1, i_w3 = -1;
    int i_b1 = -1, i_b2 = -1, i_b3 = -1;
    for (int i = 0; i < n_in; i++) {
        int s = in_sizes[i];
        if      (s == 12800000) i_x  = i;
        else if (s == 3200000)  i_ei = i;
        else if (s == 8192)     i_w1 = i;
        else if (s == 4096)     i_w2 = i;
        else if (s == 2560)     i_w3 = i;
        else if (s == 40)       i_b3 = i;
        else if (s == 64)       { if (i_b1 < 0) i_b1 = i; else i_b2 = i; }
    }
    if (i_x < 0 || i_ei < 0 || i_w1 < 0 || i_b1 < 0 || i_w2 < 0 ||
        i_b2 < 0 || i_w3 < 0 || i_b3 < 0) {
        i_x = 0; i_ei = 1; i_w1 = 2; i_b1 = 3; i_w2 = 4; i_b2 = 5; i_w3 = 6; i_b3 = 7;
    }

    const float* x  = (const float*)d_in[i_x];
    const void*  ei = d_in[i_ei];
    const float* W1 = (const float*)d_in[i_w1];
    const float* b1 = (const float*)d_in[i_b1];
    const float* W2 = (const float*)d_in[i_w2];
    const float* b2 = (const float*)d_in[i_b2];
    const float* W3 = (const float*)d_in[i_w3];
    const float* b3 = (const float*)d_in[i_b3];

    const int M = in_sizes[i_x] / 128;     // 100000
    const int E = in_sizes[i_ei] / 2;      // 1600000
    float* out = (float*)d_out;

    __half2 *pXw, *pH;
    float* pDinv;
    int *pDeg, *pCur, *pPtr, *pBsum, *pErow;
    cudaGetSymbolAddress((void**)&pXw, g_xw);
    cudaGetSymbolAddress((void**)&pH, g_h);
    cudaGetSymbolAddress((void**)&pDinv, g_dinv);
    cudaGetSymbolAddress((void**)&pDeg, g_degi);
    cudaGetSymbolAddress((void**)&pCur, g_cursor);
    cudaGetSymbolAddress((void**)&pPtr, g_ptr);
    cudaGetSymbolAddress((void**)&pBsum, g_bsum);
    cudaGetSymbolAddress((void**)&pErow, g_erow);

    const int T = 256;
    const int nbN = (M + 255) / 256;
    const int nbE = (E + T - 1) / T;
    const int gM  = (M + 127) / 128;
    const int g64 = (M + 7) / 8;
    const int g40 = (M + 11) / 12;

    cudaStream_t s2;
    cudaEvent_t evD, evF;
    bool forked = (cudaStreamCreateWithFlags(&s2, cudaStreamNonBlocking) == cudaSuccess) &&
                  (cudaEventCreateWithFlags(&evD, cudaEventDisableTiming) == cudaSuccess) &&
                  (cudaEventCreateWithFlags(&evF, cudaEventDisableTiming) == cudaSuccess);

    if (forked) {
        // side stream: complete CSR build (chained scan, no spin-waits)
        cudaEventRecord(evD, 0);
        cudaStreamWaitEvent(s2, evD, 0);
        detect_mode_kernel<<<1, 256, 0, s2>>>(ei, 2 * E, M);
        cudaMemsetAsync(pDeg, 0, (size_t)M * sizeof(int), s2);
        deg_count_kernel<<<nbE, T, 0, s2>>>(pDeg, ei, E, M);
        scanA_kernel<<<nbN, 256, 0, s2>>>(pDeg, pPtr, pBsum, M);
        scanB_kernel<<<1, 1024, 0, s2>>>(pBsum, nbN);
        scanC_fused_kernel<<<nbN, 256, 0, s2>>>(pPtr, pBsum, pCur, pDinv, pDeg, M, E);
        fill_kernel<<<nbE, T, 0, s2>>>(ei, pCur, pErow, E, M);
        cudaEventRecord(evF, s2);

        // main stream: GEMM1 (unscaled -> no dinv dependency)
        gemm_kernel<128, 64, false, false><<<gM, 128>>>(x, W1, pDinv, pXw, M);
        cudaStreamWaitEvent(0, evF, 0);
    } else {
        detect_mode_kernel<<<1, 256>>>(ei, 2 * E, M);
        cudaMemsetAsync(pDeg, 0, (size_t)M * sizeof(int), 0);
        deg_count_kernel<<<nbE, T>>>(pDeg, ei, E, M);
        scanA_kernel<<<nbN, 256>>>(pDeg, pPtr, pBsum, M);
        scanB_kernel<<<1, 1024>>>(pBsum, nbN);
        scanC_fused_kernel<<<nbN, 256>>>(pPtr, pBsum, pCur, pDinv, pDeg, M, E);
        fill_kernel<<<nbE, T>>>(ei, pCur, pErow, E, M);
        gemm_kernel<128, 64, false, false><<<gM, 128>>>(x, W1, pDinv, pXw, M);
    }

    // Layer 1 aggregation (per-neighbor dinv scaling) -> h (fp16)
    gather64h_kernel<true><<<g64, 256>>>(pXw, pPtr, pErow, pDinv, b1, pH, M);

    // Layer 2 (prescaled)
    gemm_kernel<64, 64, true, true><<<gM, 128>>>(pH, W2, pDinv, pXw, M);
    gather64h_kernel<false><<<g64, 256>>>(pXw, pPtr, pErow, pDinv, b2, pH, M);

    // Layer 3 (DOUT=40, padded stride, prescaled)
    gemm_kernel<64, 40, true, true><<<gM, 128>>>(pH, W3, pDinv, pXw, M);
    gather40_kernel<<<g40, 256>>>(pXw, pPtr, pErow, pDinv, b3, out, M);
}